// round 2
// baseline (speedup 1.0000x reference)
#include <cuda_runtime.h>
#include <cstdint>

#define E_DIM 512
#define NH    8
#define HD    64
#define BB    8
#define NPAD  1025
#define NTOK  1024
#define MTOT  (BB * NPAD)   // 8200

// Scratch (allocation-free rule: __device__ globals)
__device__ float g_q[BB * NH * NPAD * HD];
__device__ float g_k[BB * NH * NPAD * HD];
__device__ float g_v[BB * NH * NPAD * HD];
__device__ float g_att[BB * NPAD * E_DIM];

// ---------------------------------------------------------------------------
// Linear: C = A @ W^T + b.  A:[MTOT,512] row-major, W:[512,512] row-major.
// qkv_mode=1: A=Ain(x), blockIdx.z selects (W0,b0)->g_q, (W1,b1)->g_k,
//             (W2,b2)->g_v, output written in [B,H,NP,D] layout.
// qkv_mode=0: A=g_att, uses W0/b0, plain row-major store to outp.
// 128x128 tile, BK=8, 256 threads, 8x8 microtile.
// ---------------------------------------------------------------------------
__global__ __launch_bounds__(256) void linear_gemm(
    const float* __restrict__ Ain,
    const float* __restrict__ W0, const float* __restrict__ b0,
    const float* __restrict__ W1, const float* __restrict__ b1,
    const float* __restrict__ W2, const float* __restrict__ b2,
    float* __restrict__ outp, int qkv_mode)
{
    const float* A; const float* W; const float* bias; float* dst;
    if (qkv_mode) {
        A = Ain;
        int z = blockIdx.z;
        if (z == 0)      { W = W0; bias = b0; dst = g_q; }
        else if (z == 1) { W = W1; bias = b1; dst = g_k; }
        else             { W = W2; bias = b2; dst = g_v; }
    } else {
        A = g_att; W = W0; bias = b0; dst = outp;
    }

    __shared__ float As[8][128];
    __shared__ float Bs[8][128];

    const int tid = threadIdx.x;
    const int tx = tid & 15, ty = tid >> 4;
    const int m0 = blockIdx.y * 128;
    const int n0 = blockIdx.x * 128;

    const int lrow = tid >> 1;         // 0..127
    const int lk4  = (tid & 1) * 4;    // 0 or 4

    float acc[8][8];
#pragma unroll
    for (int i = 0; i < 8; i++)
#pragma unroll
        for (int j = 0; j < 8; j++) acc[i][j] = 0.f;

    for (int kt = 0; kt < 64; ++kt) {
        const int ks = kt * 8 + lk4;
        float4 av = make_float4(0.f, 0.f, 0.f, 0.f);
        const int am = m0 + lrow;
        if (am < MTOT)
            av = *reinterpret_cast<const float4*>(&A[am * 512 + ks]);
        As[lk4 + 0][lrow] = av.x; As[lk4 + 1][lrow] = av.y;
        As[lk4 + 2][lrow] = av.z; As[lk4 + 3][lrow] = av.w;

        const float4 wv = *reinterpret_cast<const float4*>(&W[(n0 + lrow) * 512 + ks]);
        Bs[lk4 + 0][lrow] = wv.x; Bs[lk4 + 1][lrow] = wv.y;
        Bs[lk4 + 2][lrow] = wv.z; Bs[lk4 + 3][lrow] = wv.w;
        __syncthreads();

#pragma unroll
        for (int kk = 0; kk < 8; kk++) {
            const float4 a0 = *reinterpret_cast<const float4*>(&As[kk][ty * 8]);
            const float4 a1 = *reinterpret_cast<const float4*>(&As[kk][ty * 8 + 4]);
            const float4 c0 = *reinterpret_cast<const float4*>(&Bs[kk][tx * 8]);
            const float4 c1 = *reinterpret_cast<const float4*>(&Bs[kk][tx * 8 + 4]);
            const float aa[8] = {a0.x, a0.y, a0.z, a0.w, a1.x, a1.y, a1.z, a1.w};
            const float bb[8] = {c0.x, c0.y, c0.z, c0.w, c1.x, c1.y, c1.z, c1.w};
#pragma unroll
            for (int i = 0; i < 8; i++)
#pragma unroll
                for (int j = 0; j < 8; j++) acc[i][j] += aa[i] * bb[j];
        }
        __syncthreads();
    }

#pragma unroll
    for (int i = 0; i < 8; i++) {
        const int m = m0 + ty * 8 + i;
        if (m >= MTOT) continue;
#pragma unroll
        for (int j = 0; j < 8; j++) {
            const int n = n0 + tx * 8 + j;
            const float v = acc[i][j] + bias[n];
            if (qkv_mode) {
                const int b = m / NPAD, row = m % NPAD;
                const int h = n >> 6, d = n & 63;
                dst[((b * NH + h) * NPAD + row) * HD + d] = v;
            } else {
                dst[m * 512 + n] = v;
            }
        }
    }
}

// ---------------------------------------------------------------------------
// Flash-style attention. One CTA per (qtile=64 rows, head, batch).
// smem: Qs[q][d], Kt[d][key] (transposed: conflict-free LDS.128),
//       Vs[key][d], Ps[q][key].  256 threads, 4x4 microtile each.
// Online softmax with -1e30 masking; p forced to 0 for masked entries.
// NOTE: pad_mask is bool in the reference -> harness upcasts to int32.
// ---------------------------------------------------------------------------
__global__ __launch_bounds__(256) void attn_kernel(
    const float* __restrict__ bias, const int* __restrict__ mask)
{
    extern __shared__ float sm[];
    float* Qs = sm;            // 64*64
    float* Kt = sm + 4096;     // 64*64  (row = d, col = key)
    float* Vs = sm + 8192;     // 64*64  (row = key, col = d)
    float* Ps = sm + 12288;    // 64*64  (row = q, col = key)

    const int tid = threadIdx.x;
    const int tx = tid & 15, ty = tid >> 4;
    const int qt = blockIdx.x, h = blockIdx.y, b = blockIdx.z;
    const int qbase = qt * 64;

    const float* qptr = g_q + (size_t)((b * NH + h) * NPAD) * HD;
    const float* kptr = g_k + (size_t)((b * NH + h) * NPAD) * HD;
    const float* vptr = g_v + (size_t)((b * NH + h) * NPAD) * HD;
    const float* bptr = bias + (size_t)((b * NH + h) * NPAD) * NPAD;

    // Load Q tile once
#pragma unroll
    for (int it = 0; it < 4; ++it) {
        const int lin = tid + it * 256;         // 0..1023 float4-chunks
        const int r = lin >> 4;                 // 0..63
        const int c4 = (lin & 15) * 4;          // 0..60
        float4 v = make_float4(0.f, 0.f, 0.f, 0.f);
        const int qrow = qbase + r;
        if (qrow < NPAD)
            v = *reinterpret_cast<const float4*>(&qptr[qrow * HD + c4]);
        *reinterpret_cast<float4*>(&Qs[r * 64 + c4]) = v;
    }

    float m_i[4], l_i[4], o[4][4];
#pragma unroll
    for (int i = 0; i < 4; i++) {
        m_i[i] = -1e30f; l_i[i] = 0.f;
#pragma unroll
        for (int j = 0; j < 4; j++) o[i][j] = 0.f;
    }

    for (int kt = 0; kt < 17; ++kt) {
        const int kbase = kt * 64;
        // Load K (transposed) and V tiles
#pragma unroll
        for (int it = 0; it < 4; ++it) {
            const int lin = tid + it * 256;
            const int r = lin >> 4;
            const int c4 = (lin & 15) * 4;
            const int krow = kbase + r;
            float4 kv = make_float4(0.f, 0.f, 0.f, 0.f);
            float4 vv = make_float4(0.f, 0.f, 0.f, 0.f);
            if (krow < NPAD) {
                kv = *reinterpret_cast<const float4*>(&kptr[krow * HD + c4]);
                vv = *reinterpret_cast<const float4*>(&vptr[krow * HD + c4]);
            }
            Kt[(c4 + 0) * 64 + r] = kv.x;
            Kt[(c4 + 1) * 64 + r] = kv.y;
            Kt[(c4 + 2) * 64 + r] = kv.z;
            Kt[(c4 + 3) * 64 + r] = kv.w;
            *reinterpret_cast<float4*>(&Vs[r * 64 + c4]) = vv;
        }
        __syncthreads();

        // S = Q K^T  (thread owns rows ty*4.., cols tx*4..)
        float s[4][4];
#pragma unroll
        for (int i = 0; i < 4; i++)
#pragma unroll
            for (int j = 0; j < 4; j++) s[i][j] = 0.f;

#pragma unroll
        for (int d4 = 0; d4 < 16; ++d4) {
            float4 qa[4], kb[4];
#pragma unroll
            for (int i = 0; i < 4; i++)
                qa[i] = *reinterpret_cast<const float4*>(&Qs[(ty * 4 + i) * 64 + d4 * 4]);
#pragma unroll
            for (int dd = 0; dd < 4; dd++)
                kb[dd] = *reinterpret_cast<const float4*>(&Kt[(d4 * 4 + dd) * 64 + tx * 4]);
#pragma unroll
            for (int i = 0; i < 4; i++) {
                s[i][0] += qa[i].x * kb[0].x + qa[i].y * kb[1].x + qa[i].z * kb[2].x + qa[i].w * kb[3].x;
                s[i][1] += qa[i].x * kb[0].y + qa[i].y * kb[1].y + qa[i].z * kb[2].y + qa[i].w * kb[3].y;
                s[i][2] += qa[i].x * kb[0].z + qa[i].y * kb[1].z + qa[i].z * kb[2].z + qa[i].w * kb[3].z;
                s[i][3] += qa[i].x * kb[0].w + qa[i].y * kb[1].w + qa[i].z * kb[2].w + qa[i].w * kb[3].w;
            }
        }

        // scale + bias + padding mask (mask is int32: harness upcasts bool)
#pragma unroll
        for (int i = 0; i < 4; i++) {
            const int qrow = qbase + ty * 4 + i;
#pragma unroll
            for (int j = 0; j < 4; j++) {
                const int kcol = kbase + tx * 4 + j;
                float val = -1e30f;
                if (qrow < NPAD && kcol < NPAD) {
                    val = s[i][j] * 0.125f + __ldg(&bptr[qrow * NPAD + kcol]);
                    if (qrow > 0 && kcol > 0) {
                        if (__ldg(&mask[(b * NTOK + (qrow - 1)) * NTOK + (kcol - 1)]) == 0)
                            val = -1e30f;
                    }
                }
                s[i][j] = val;
            }
        }

        // online softmax (row spread over 16 lanes sharing ty)
#pragma unroll
        for (int i = 0; i < 4; i++) {
            float mx = fmaxf(fmaxf(s[i][0], s[i][1]), fmaxf(s[i][2], s[i][3]));
#pragma unroll
            for (int off = 1; off < 16; off <<= 1)
                mx = fmaxf(mx, __shfl_xor_sync(0xffffffffu, mx, off));
            const float mn = fmaxf(m_i[i], mx);
            const float corr = __expf(m_i[i] - mn);
            m_i[i] = mn;
            float rs = 0.f;
#pragma unroll
            for (int j = 0; j < 4; j++) {
                // masked entries contribute exactly 0 (avoid exp(0)=1 traps)
                const float p = (s[i][j] > -1e29f) ? __expf(s[i][j] - mn) : 0.f;
                s[i][j] = p;
                rs += p;
            }
#pragma unroll
            for (int off = 1; off < 16; off <<= 1)
                rs += __shfl_xor_sync(0xffffffffu, rs, off);
            l_i[i] = l_i[i] * corr + rs;
#pragma unroll
            for (int j = 0; j < 4; j++) o[i][j] *= corr;

            float4 pv = make_float4(s[i][0], s[i][1], s[i][2], s[i][3]);
            *reinterpret_cast<float4*>(&Ps[(ty * 4 + i) * 64 + tx * 4]) = pv;
        }
        __syncthreads();

        // O += P V  (thread owns rows ty*4.., d-cols tx*4..)
#pragma unroll
        for (int k4 = 0; k4 < 16; ++k4) {
            float4 pa[4], vb[4];
#pragma unroll
            for (int i = 0; i < 4; i++)
                pa[i] = *reinterpret_cast<const float4*>(&Ps[(ty * 4 + i) * 64 + k4 * 4]);
#pragma unroll
            for (int kk = 0; kk < 4; kk++)
                vb[kk] = *reinterpret_cast<const float4*>(&Vs[(k4 * 4 + kk) * 64 + tx * 4]);
#pragma unroll
            for (int i = 0; i < 4; i++) {
                o[i][0] += pa[i].x * vb[0].x + pa[i].y * vb[1].x + pa[i].z * vb[2].x + pa[i].w * vb[3].x;
                o[i][1] += pa[i].x * vb[0].y + pa[i].y * vb[1].y + pa[i].z * vb[2].y + pa[i].w * vb[3].y;
                o[i][2] += pa[i].x * vb[0].z + pa[i].y * vb[1].z + pa[i].z * vb[2].z + pa[i].w * vb[3].z;
                o[i][3] += pa[i].x * vb[0].w + pa[i].y * vb[1].w + pa[i].z * vb[2].w + pa[i].w * vb[3].w;
            }
        }
        __syncthreads();
    }

    // normalize + store in [B,NP,H*D] layout (ready for out-projection)
#pragma unroll
    for (int i = 0; i < 4; i++) {
        const int qrow = qbase + ty * 4 + i;
        if (qrow < NPAD) {
            const float inv = 1.f / l_i[i];
            float4 r = make_float4(o[i][0] * inv, o[i][1] * inv, o[i][2] * inv, o[i][3] * inv);
            *reinterpret_cast<float4*>(&g_att[(size_t)(b * NPAD + qrow) * E_DIM + h * HD + tx * 4]) = r;
        }
    }
}

// ---------------------------------------------------------------------------
extern "C" void kernel_launch(void* const* d_in, const int* in_sizes, int n_in,
                              void* d_out, int out_size)
{
    const float* x  = (const float*)d_in[0];
    const float* ab = (const float*)d_in[1];
    const int*   pm = (const int*)d_in[2];
    const float* Wq = (const float*)d_in[3];
    const float* bq = (const float*)d_in[4];
    const float* Wk = (const float*)d_in[5];
    const float* bk = (const float*)d_in[6];
    const float* Wv = (const float*)d_in[7];
    const float* bv = (const float*)d_in[8];
    const float* Wo = (const float*)d_in[9];
    const float* bo = (const float*)d_in[10];
    float* out = (float*)d_out;

    cudaFuncSetAttribute(attn_kernel,
                         cudaFuncAttributeMaxDynamicSharedMemorySize, 65536);

    // QKV projections (z selects Q/K/V)
    dim3 gq(4, 65, 3);
    linear_gemm<<<gq, 256>>>(x, Wq, bq, Wk, bk, Wv, bv, nullptr, 1);

    // attention
    attn_kernel<<<dim3(17, NH, BB), 256, 65536>>>(ab, pm);

    // output projection
    dim3 go(4, 65, 1);
    linear_gemm<<<go, 256>>>(nullptr, Wo, bo, nullptr, nullptr, nullptr, nullptr, out, 0);
}

// round 4
// speedup vs baseline: 1.7590x; 1.7590x over previous
#include <cuda_runtime.h>
#include <cstdint>

#define E_DIM 512
#define NH    8
#define HD    64
#define BB    8
#define NPAD  1025
#define NTOK  1024
#define MTOT  (BB * NPAD)   // 8200
#define MWORDS 34           // ceil(1025/32)+pad

// Scratch (allocation-free rule: __device__ globals)
__device__ float g_q[BB * NH * NPAD * HD];
__device__ float g_k[BB * NH * NPAD * HD];
__device__ float g_v[BB * NH * NPAD * HD];
__device__ float g_att[BB * NPAD * E_DIM];
__device__ uint32_t g_mbits[BB * NPAD * MWORDS];

__device__ __forceinline__ uint32_t f2t(float x) {
    uint32_t u;
    asm("cvt.rna.tf32.f32 %0, %1;" : "=r"(u) : "f"(x));
    return u;
}

// D += A(16x8,row) * B(8x8,col), tf32 inputs, fp32 accum
__device__ __forceinline__ void mma8(float* c, const uint32_t* a, const uint32_t* b) {
    asm volatile(
        "mma.sync.aligned.m16n8k8.row.col.f32.tf32.tf32.f32 "
        "{%0,%1,%2,%3}, {%4,%5,%6,%7}, {%8,%9}, {%0,%1,%2,%3};\n"
        : "+f"(c[0]), "+f"(c[1]), "+f"(c[2]), "+f"(c[3])
        : "r"(a[0]), "r"(a[1]), "r"(a[2]), "r"(a[3]), "r"(b[0]), "r"(b[1]));
}

// ---------------------------------------------------------------------------
// Pack pad_mask (int32 0/1, [B,N,N]) into bitmask over the padded [NP,NP] grid.
// bit=1 => keep. Row 0 / col 0 (graph token) always keep. OOB cols => 0.
// ---------------------------------------------------------------------------
__global__ void pack_mask(const int* __restrict__ pm) {
    int idx = blockIdx.x * 256 + threadIdx.x;
    const int total = BB * NPAD * MWORDS;
    if (idx >= total) return;
    int w = idx % MWORDS;
    int row = (idx / MWORDS) % NPAD;
    int b = idx / (MWORDS * NPAD);
    uint32_t bits = 0;
    for (int i = 0; i < 32; i++) {
        int col = w * 32 + i;
        if (col >= NPAD) break;
        bool keep;
        if (row == 0 || col == 0) keep = true;
        else keep = __ldg(&pm[(b * NTOK + row - 1) * NTOK + col - 1]) != 0;
        if (keep) bits |= (1u << i);
    }
    g_mbits[idx] = bits;
}

// ---------------------------------------------------------------------------
// Linear: C = A @ W^T + b via tf32 mma. 128x128 CTA tile, K-chunk 32.
// 8 warps, warp tile 32(M) x 64(N): 2 m-tiles x 8 n-tiles of m16n8k8.
// qkv_mode=1: A=x, z selects Q/K/V weights, scatter to [B,H,NP,D].
// qkv_mode=0: A=g_att, W0/b0, row-major store to outp.
// ---------------------------------------------------------------------------
__global__ __launch_bounds__(256) void linear_tf32(
    const float* __restrict__ Ain,
    const float* __restrict__ W0, const float* __restrict__ b0,
    const float* __restrict__ W1, const float* __restrict__ b1,
    const float* __restrict__ W2, const float* __restrict__ b2,
    float* __restrict__ outp, int qkv_mode)
{
    const float* A; const float* W; const float* bias; float* dst;
    if (qkv_mode) {
        A = Ain;
        int z = blockIdx.z;
        if (z == 0)      { W = W0; bias = b0; dst = g_q; }
        else if (z == 1) { W = W1; bias = b1; dst = g_k; }
        else             { W = W2; bias = b2; dst = g_v; }
    } else {
        A = g_att; W = W0; bias = b0; dst = outp;
    }

    __shared__ uint32_t As[32][136];   // [k][m], stride 136 -> bank = 8k+m
    __shared__ uint32_t Ws[32][136];   // [k][n]

    const int tid  = threadIdx.x;
    const int lane = tid & 31, warp = tid >> 5;
    const int g = lane >> 2, tig = lane & 3;
    const int wm = (warp & 3) * 32;      // warp m-offset in CTA tile
    const int wn = (warp >> 2) * 64;     // warp n-offset
    const int m0 = blockIdx.y * 128;
    const int n0 = blockIdx.x * 128;

    const int lrow = tid >> 1;           // 0..127
    const int lk   = (tid & 1) * 16;     // 0 or 16

    float c[2][8][4];
#pragma unroll
    for (int mt = 0; mt < 2; mt++)
#pragma unroll
        for (int nt = 0; nt < 8; nt++)
#pragma unroll
            for (int e = 0; e < 4; e++) c[mt][nt][e] = 0.f;

    for (int kc = 0; kc < 512; kc += 32) {
        // Load A tile (128 x 32), transpose+convert into As[k][m]
        {
            const int am = m0 + lrow;
            const bool ok = am < MTOT;
#pragma unroll
            for (int q = 0; q < 4; q++) {
                float4 v = ok ? *reinterpret_cast<const float4*>(&A[(size_t)am * 512 + kc + lk + 4 * q])
                              : make_float4(0.f, 0.f, 0.f, 0.f);
                As[lk + 4 * q + 0][lrow] = f2t(v.x);
                As[lk + 4 * q + 1][lrow] = f2t(v.y);
                As[lk + 4 * q + 2][lrow] = f2t(v.z);
                As[lk + 4 * q + 3][lrow] = f2t(v.w);
            }
        }
        // Load W tile (128 rows of n, 32 k) into Ws[k][n]
        {
            const int nr = n0 + lrow;   // < 512 always
#pragma unroll
            for (int q = 0; q < 4; q++) {
                float4 v = *reinterpret_cast<const float4*>(&W[(size_t)nr * 512 + kc + lk + 4 * q]);
                Ws[lk + 4 * q + 0][lrow] = f2t(v.x);
                Ws[lk + 4 * q + 1][lrow] = f2t(v.y);
                Ws[lk + 4 * q + 2][lrow] = f2t(v.z);
                Ws[lk + 4 * q + 3][lrow] = f2t(v.w);
            }
        }
        __syncthreads();

#pragma unroll
        for (int ks = 0; ks < 32; ks += 8) {
            uint32_t a[2][4];
#pragma unroll
            for (int mt = 0; mt < 2; mt++) {
                const int mm = wm + mt * 16 + g;
                a[mt][0] = As[ks + tig][mm];
                a[mt][1] = As[ks + tig][mm + 8];
                a[mt][2] = As[ks + tig + 4][mm];
                a[mt][3] = As[ks + tig + 4][mm + 8];
            }
            uint32_t bfr[8][2];
#pragma unroll
            for (int nt = 0; nt < 8; nt++) {
                const int nn = wn + nt * 8 + g;
                bfr[nt][0] = Ws[ks + tig][nn];
                bfr[nt][1] = Ws[ks + tig + 4][nn];
            }
#pragma unroll
            for (int mt = 0; mt < 2; mt++)
#pragma unroll
                for (int nt = 0; nt < 8; nt++)
                    mma8(c[mt][nt], a[mt], bfr[nt]);
        }
        __syncthreads();
    }

    // Epilogue
#pragma unroll
    for (int mt = 0; mt < 2; mt++) {
        const int mA = m0 + wm + mt * 16 + g;
#pragma unroll
        for (int i = 0; i < 2; i++) {       // row g / g+8
            const int m = mA + 8 * i;
            if (m >= MTOT) continue;
            int bq_ = 0, rq = 0;
            if (qkv_mode) { bq_ = m / NPAD; rq = m % NPAD; }
#pragma unroll
            for (int nt = 0; nt < 8; nt++) {
                const int n = n0 + wn + nt * 8 + 2 * tig;
                float2 v = make_float2(c[mt][nt][2 * i + 0] + bias[n],
                                       c[mt][nt][2 * i + 1] + bias[n + 1]);
                if (qkv_mode) {
                    const int hh = n >> 6, d = n & 63;
                    *reinterpret_cast<float2*>(
                        &dst[(((size_t)bq_ * NH + hh) * NPAD + rq) * HD + d]) = v;
                } else {
                    *reinterpret_cast<float2*>(&dst[(size_t)m * 512 + n]) = v;
                }
            }
        }
    }
}

// ---------------------------------------------------------------------------
// Flash attention with tf32 mma. CTA: 64 q-rows, 128 threads (4 warps),
// warp owns 16 q-rows x full 64-key tile. 17 key tiles.
// smem (tf32-converted): Qs/Ks/Ps stride 68, Vs stride 72, mask bits.
// NOTE: bias rows have odd element stride (NPAD=1025) -> scalar loads only.
// ---------------------------------------------------------------------------
__global__ __launch_bounds__(128) void attn_tf32(const float* __restrict__ bias)
{
    extern __shared__ uint32_t sm[];
    uint32_t* Qs = sm;                  // [64][68]
    uint32_t* Ks = Qs + 64 * 68;        // [64][68]
    uint32_t* Ps = Ks + 64 * 68;        // [64][68]
    uint32_t* Vs = Ps + 64 * 68;        // [64][72]
    uint32_t* Mk = Vs + 64 * 72;        // [64][2]

    const int tid  = threadIdx.x;
    const int lane = tid & 31, warp = tid >> 5;
    const int g = lane >> 2, tig = lane & 3;
    const int qt = blockIdx.x, h = blockIdx.y, b = blockIdx.z;
    const int qbase = qt * 64, slab = warp * 16;

    const float* qptr = g_q + (size_t)((b * NH + h) * NPAD) * HD;
    const float* kptr = g_k + (size_t)((b * NH + h) * NPAD) * HD;
    const float* vptr = g_v + (size_t)((b * NH + h) * NPAD) * HD;
    const float* bptr = bias + (size_t)(b * NH + h) * NPAD * NPAD;

    // Load + convert Q tile
    {
        const int r = tid >> 1, c0 = (tid & 1) * 32;
        const int qrow = qbase + r;
        const bool ok = qrow < NPAD;
#pragma unroll
        for (int j = 0; j < 8; j++) {
            float4 v = ok ? *reinterpret_cast<const float4*>(&qptr[(size_t)qrow * HD + c0 + 4 * j])
                          : make_float4(0.f, 0.f, 0.f, 0.f);
            uint4 u = make_uint4(f2t(v.x), f2t(v.y), f2t(v.z), f2t(v.w));
            *reinterpret_cast<uint4*>(&Qs[r * 68 + c0 + 4 * j]) = u;
        }
    }

    float mrow[2] = {-1e30f, -1e30f}, lsum[2] = {0.f, 0.f};
    float o[8][4];
#pragma unroll
    for (int nt = 0; nt < 8; nt++)
#pragma unroll
        for (int e = 0; e < 4; e++) o[nt][e] = 0.f;

    for (int kt = 0; kt < 17; kt++) {
        const int kbase = kt * 64;
        // Load K, V tiles (+ convert) and mask words
        {
            const int r = tid >> 1, c0 = (tid & 1) * 32;
            const int krow = kbase + r;
            const bool ok = krow < NPAD;
#pragma unroll
            for (int j = 0; j < 8; j++) {
                float4 kv = ok ? *reinterpret_cast<const float4*>(&kptr[(size_t)krow * HD + c0 + 4 * j])
                               : make_float4(0.f, 0.f, 0.f, 0.f);
                float4 vv = ok ? *reinterpret_cast<const float4*>(&vptr[(size_t)krow * HD + c0 + 4 * j])
                               : make_float4(0.f, 0.f, 0.f, 0.f);
                *reinterpret_cast<uint4*>(&Ks[r * 68 + c0 + 4 * j]) =
                    make_uint4(f2t(kv.x), f2t(kv.y), f2t(kv.z), f2t(kv.w));
                *reinterpret_cast<uint4*>(&Vs[r * 72 + c0 + 4 * j]) =
                    make_uint4(f2t(vv.x), f2t(vv.y), f2t(vv.z), f2t(vv.w));
            }
            const int mr = tid >> 1, w = tid & 1;
            const int qrow = qbase + mr;
            Mk[mr * 2 + w] = (qrow < NPAD)
                ? g_mbits[((size_t)b * NPAD + qrow) * MWORDS + 2 * kt + w] : 0u;
        }
        __syncthreads();

        // S = Q K^T for this warp's 16 rows x 64 cols
        float s[8][4];
#pragma unroll
        for (int nt = 0; nt < 8; nt++)
#pragma unroll
            for (int e = 0; e < 4; e++) s[nt][e] = 0.f;

#pragma unroll
        for (int kc = 0; kc < 64; kc += 8) {
            uint32_t a[4];
            a[0] = Qs[(slab + g) * 68 + kc + tig];
            a[1] = Qs[(slab + g + 8) * 68 + kc + tig];
            a[2] = Qs[(slab + g) * 68 + kc + tig + 4];
            a[3] = Qs[(slab + g + 8) * 68 + kc + tig + 4];
#pragma unroll
            for (int nt = 0; nt < 8; nt++) {
                uint32_t bf[2];
                bf[0] = Ks[(nt * 8 + g) * 68 + kc + tig];
                bf[1] = Ks[(nt * 8 + g) * 68 + kc + tig + 4];
                mma8(s[nt], a, bf);
            }
        }

        // scale + bias + mask fixup (scalar bias loads: NPAD odd => no float2)
#pragma unroll
        for (int i = 0; i < 2; i++) {
            const int row = qbase + slab + g + 8 * i;
            const bool rok = row < NPAD;
            const uint32_t w0 = Mk[(slab + g + 8 * i) * 2];
            const uint32_t w1 = Mk[(slab + g + 8 * i) * 2 + 1];
            const float* brow = bptr + (size_t)row * NPAD + kbase;
#pragma unroll
            for (int nt = 0; nt < 8; nt++) {
                const int j = nt * 8 + 2 * tig;
                float b0v = 0.f, b1v = 0.f;
                if (rok) {
                    if (kbase + j < NPAD)     b0v = __ldg(&brow[j]);
                    if (kbase + j + 1 < NPAD) b1v = __ldg(&brow[j + 1]);
                }
                float v0 = s[nt][2 * i]     * 0.125f + b0v;
                float v1 = s[nt][2 * i + 1] * 0.125f + b1v;
                const uint32_t w = (j < 32) ? w0 : w1;
                if (!((w >> (j & 31)) & 1u))       v0 = -1e30f;
                if (!((w >> ((j + 1) & 31)) & 1u)) v1 = -1e30f;
                if (!rok || kbase + j >= NPAD)     v0 = -1e30f;
                if (!rok || kbase + j + 1 >= NPAD) v1 = -1e30f;
                s[nt][2 * i] = v0; s[nt][2 * i + 1] = v1;
            }
        }

        // online softmax (quad reductions) + write P (tf32) to warp-private Ps
#pragma unroll
        for (int i = 0; i < 2; i++) {
            float mx = -1e30f;
#pragma unroll
            for (int nt = 0; nt < 8; nt++)
                mx = fmaxf(mx, fmaxf(s[nt][2 * i], s[nt][2 * i + 1]));
            mx = fmaxf(mx, __shfl_xor_sync(0xffffffffu, mx, 1));
            mx = fmaxf(mx, __shfl_xor_sync(0xffffffffu, mx, 2));
            const float mn = fmaxf(mrow[i], mx);
            const float corr = __expf(mrow[i] - mn);
            float rs = 0.f;
#pragma unroll
            for (int nt = 0; nt < 8; nt++) {
                float p0 = (s[nt][2 * i]     > -1e29f) ? __expf(s[nt][2 * i]     - mn) : 0.f;
                float p1 = (s[nt][2 * i + 1] > -1e29f) ? __expf(s[nt][2 * i + 1] - mn) : 0.f;
                s[nt][2 * i] = p0; s[nt][2 * i + 1] = p1;
                rs += p0 + p1;
            }
            rs += __shfl_xor_sync(0xffffffffu, rs, 1);
            rs += __shfl_xor_sync(0xffffffffu, rs, 2);
            mrow[i] = mn;
            lsum[i] = lsum[i] * corr + rs;
#pragma unroll
            for (int nt = 0; nt < 8; nt++) {
                o[nt][2 * i]     *= corr;
                o[nt][2 * i + 1] *= corr;
            }
#pragma unroll
            for (int nt = 0; nt < 8; nt++) {
                uint2 u = make_uint2(f2t(s[nt][2 * i]), f2t(s[nt][2 * i + 1]));
                *reinterpret_cast<uint2*>(&Ps[(slab + g + 8 * i) * 68 + nt * 8 + 2 * tig]) = u;
            }
        }
        __syncwarp();

        // O += P V
#pragma unroll
        for (int kc = 0; kc < 64; kc += 8) {
            uint32_t a[4];
            a[0] = Ps[(slab + g) * 68 + kc + tig];
            a[1] = Ps[(slab + g + 8) * 68 + kc + tig];
            a[2] = Ps[(slab + g) * 68 + kc + tig + 4];
            a[3] = Ps[(slab + g + 8) * 68 + kc + tig + 4];
#pragma unroll
            for (int nt = 0; nt < 8; nt++) {
                uint32_t bf[2];
                bf[0] = Vs[(kc + tig) * 72 + nt * 8 + g];
                bf[1] = Vs[(kc + tig + 4) * 72 + nt * 8 + g];
                mma8(o[nt], a, bf);
            }
        }
        __syncthreads();
    }

    // epilogue: normalize + store [B,NP,H*D]
    const float inv0 = (lsum[0] > 0.f) ? 1.f / lsum[0] : 0.f;
    const float inv1 = (lsum[1] > 0.f) ? 1.f / lsum[1] : 0.f;
    const int r0 = qbase + slab + g;
    float* obase = g_att + (size_t)b * NPAD * E_DIM + h * HD;
#pragma unroll
    for (int nt = 0; nt < 8; nt++) {
        const int d = nt * 8 + 2 * tig;
        if (r0 < NPAD)
            *reinterpret_cast<float2*>(&obase[(size_t)r0 * E_DIM + d]) =
                make_float2(o[nt][0] * inv0, o[nt][1] * inv0);
        if (r0 + 8 < NPAD)
            *reinterpret_cast<float2*>(&obase[(size_t)(r0 + 8) * E_DIM + d]) =
                make_float2(o[nt][2] * inv1, o[nt][3] * inv1);
    }
}

// ---------------------------------------------------------------------------
extern "C" void kernel_launch(void* const* d_in, const int* in_sizes, int n_in,
                              void* d_out, int out_size)
{
    const float* x  = (const float*)d_in[0];
    const float* ab = (const float*)d_in[1];
    const int*   pm = (const int*)d_in[2];
    const float* Wq = (const float*)d_in[3];
    const float* bq = (const float*)d_in[4];
    const float* Wk = (const float*)d_in[5];
    const float* bk = (const float*)d_in[6];
    const float* Wv = (const float*)d_in[7];
    const float* bv = (const float*)d_in[8];
    const float* Wo = (const float*)d_in[9];
    const float* bo = (const float*)d_in[10];
    float* out = (float*)d_out;

    const int ATTN_SMEM = (3 * 64 * 68 + 64 * 72 + 128) * 4;  // 71168 B
    cudaFuncSetAttribute(attn_tf32,
                         cudaFuncAttributeMaxDynamicSharedMemorySize, ATTN_SMEM);

    pack_mask<<<(BB * NPAD * MWORDS + 255) / 256, 256>>>(pm);

    dim3 gq(4, 65, 3);
    linear_tf32<<<gq, 256>>>(x, Wq, bq, Wk, bk, Wv, bv, nullptr, 1);

    attn_tf32<<<dim3(17, NH, BB), 128, ATTN_SMEM>>>(ab);

    dim3 go(4, 65, 1);
    linear_tf32<<<go, 256>>>(nullptr, Wo, bo, nullptr, nullptr, nullptr, nullptr, out, 0);
}

// round 5
// speedup vs baseline: 2.8130x; 1.5992x over previous
#include <cuda_runtime.h>
#include <cstdint>

#define E_DIM 512
#define NH    8
#define HD    64
#define BB    8
#define NPAD  1025
#define NTOK  1024
#define MTOT  (BB * NPAD)   // 8200
#define MWORDS 34           // ceil(1025/32)+pad

// Scratch (allocation-free rule: __device__ globals)
__device__ float g_q[BB * NH * NPAD * HD];
__device__ float g_k[BB * NH * NPAD * HD];
__device__ float g_v[BB * NH * NPAD * HD];
__device__ float g_att[BB * NPAD * E_DIM];
__device__ uint32_t g_mbits[BB * NPAD * MWORDS];

__device__ __forceinline__ uint32_t f2t(float x) {
    uint32_t u;
    asm("cvt.rna.tf32.f32 %0, %1;" : "=r"(u) : "f"(x));
    return u;
}
// pack two f32 -> half2 {lo, hi}
__device__ __forceinline__ uint32_t f2h2(float lo, float hi) {
    uint32_t r;
    asm("cvt.rn.f16x2.f32 %0, %1, %2;" : "=r"(r) : "f"(hi), "f"(lo));
    return r;
}

// D += A(16x8,row) * B(8x8,col), tf32 inputs, fp32 accum
__device__ __forceinline__ void mma8(float* c, const uint32_t* a, const uint32_t* b) {
    asm volatile(
        "mma.sync.aligned.m16n8k8.row.col.f32.tf32.tf32.f32 "
        "{%0,%1,%2,%3}, {%4,%5,%6,%7}, {%8,%9}, {%0,%1,%2,%3};\n"
        : "+f"(c[0]), "+f"(c[1]), "+f"(c[2]), "+f"(c[3])
        : "r"(a[0]), "r"(a[1]), "r"(a[2]), "r"(a[3]), "r"(b[0]), "r"(b[1]));
}
// D += A(16x16,row) * B(16x8,col), f16 inputs, fp32 accum
__device__ __forceinline__ void mma16(float* c, const uint32_t* a, const uint32_t* b) {
    asm volatile(
        "mma.sync.aligned.m16n8k16.row.col.f32.f16.f16.f32 "
        "{%0,%1,%2,%3}, {%4,%5,%6,%7}, {%8,%9}, {%0,%1,%2,%3};\n"
        : "+f"(c[0]), "+f"(c[1]), "+f"(c[2]), "+f"(c[3])
        : "r"(a[0]), "r"(a[1]), "r"(a[2]), "r"(a[3]), "r"(b[0]), "r"(b[1]));
}

// ---------------------------------------------------------------------------
// Pack pad_mask (int32 0/1, [B,N,N]) into bitmask over the padded [NP,NP] grid.
// bit=1 => keep. Row 0 / col 0 (graph token) always keep. OOB cols => 0.
// ---------------------------------------------------------------------------
__global__ void pack_mask(const int* __restrict__ pm) {
    int idx = blockIdx.x * 256 + threadIdx.x;
    const int total = BB * NPAD * MWORDS;
    if (idx >= total) return;
    int w = idx % MWORDS;
    int row = (idx / MWORDS) % NPAD;
    int b = idx / (MWORDS * NPAD);
    uint32_t bits = 0;
    for (int i = 0; i < 32; i++) {
        int col = w * 32 + i;
        if (col >= NPAD) break;
        bool keep;
        if (row == 0 || col == 0) keep = true;
        else keep = __ldg(&pm[(b * NTOK + row - 1) * NTOK + col - 1]) != 0;
        if (keep) bits |= (1u << i);
    }
    g_mbits[idx] = bits;
}

// ---------------------------------------------------------------------------
// Linear: C = A @ W^T + b via tf32 mma. 128x128 CTA tile, K-chunk 32.
// ---------------------------------------------------------------------------
__global__ __launch_bounds__(256) void linear_tf32(
    const float* __restrict__ Ain,
    const float* __restrict__ W0, const float* __restrict__ b0,
    const float* __restrict__ W1, const float* __restrict__ b1,
    const float* __restrict__ W2, const float* __restrict__ b2,
    float* __restrict__ outp, int qkv_mode)
{
    const float* A; const float* W; const float* bias; float* dst;
    if (qkv_mode) {
        A = Ain;
        int z = blockIdx.z;
        if (z == 0)      { W = W0; bias = b0; dst = g_q; }
        else if (z == 1) { W = W1; bias = b1; dst = g_k; }
        else             { W = W2; bias = b2; dst = g_v; }
    } else {
        A = g_att; W = W0; bias = b0; dst = outp;
    }

    __shared__ uint32_t As[32][136];
    __shared__ uint32_t Ws[32][136];

    const int tid  = threadIdx.x;
    const int lane = tid & 31, warp = tid >> 5;
    const int g = lane >> 2, tig = lane & 3;
    const int wm = (warp & 3) * 32;
    const int wn = (warp >> 2) * 64;
    const int m0 = blockIdx.y * 128;
    const int n0 = blockIdx.x * 128;

    const int lrow = tid >> 1;
    const int lk   = (tid & 1) * 16;

    float c[2][8][4];
#pragma unroll
    for (int mt = 0; mt < 2; mt++)
#pragma unroll
        for (int nt = 0; nt < 8; nt++)
#pragma unroll
            for (int e = 0; e < 4; e++) c[mt][nt][e] = 0.f;

    for (int kc = 0; kc < 512; kc += 32) {
        {
            const int am = m0 + lrow;
            const bool ok = am < MTOT;
#pragma unroll
            for (int q = 0; q < 4; q++) {
                float4 v = ok ? *reinterpret_cast<const float4*>(&A[(size_t)am * 512 + kc + lk + 4 * q])
                              : make_float4(0.f, 0.f, 0.f, 0.f);
                As[lk + 4 * q + 0][lrow] = f2t(v.x);
                As[lk + 4 * q + 1][lrow] = f2t(v.y);
                As[lk + 4 * q + 2][lrow] = f2t(v.z);
                As[lk + 4 * q + 3][lrow] = f2t(v.w);
            }
        }
        {
            const int nr = n0 + lrow;
#pragma unroll
            for (int q = 0; q < 4; q++) {
                float4 v = *reinterpret_cast<const float4*>(&W[(size_t)nr * 512 + kc + lk + 4 * q]);
                Ws[lk + 4 * q + 0][lrow] = f2t(v.x);
                Ws[lk + 4 * q + 1][lrow] = f2t(v.y);
                Ws[lk + 4 * q + 2][lrow] = f2t(v.z);
                Ws[lk + 4 * q + 3][lrow] = f2t(v.w);
            }
        }
        __syncthreads();

#pragma unroll
        for (int ks = 0; ks < 32; ks += 8) {
            uint32_t a[2][4];
#pragma unroll
            for (int mt = 0; mt < 2; mt++) {
                const int mm = wm + mt * 16 + g;
                a[mt][0] = As[ks + tig][mm];
                a[mt][1] = As[ks + tig][mm + 8];
                a[mt][2] = As[ks + tig + 4][mm];
                a[mt][3] = As[ks + tig + 4][mm + 8];
            }
            uint32_t bfr[8][2];
#pragma unroll
            for (int nt = 0; nt < 8; nt++) {
                const int nn = wn + nt * 8 + g;
                bfr[nt][0] = Ws[ks + tig][nn];
                bfr[nt][1] = Ws[ks + tig + 4][nn];
            }
#pragma unroll
            for (int mt = 0; mt < 2; mt++)
#pragma unroll
                for (int nt = 0; nt < 8; nt++)
                    mma8(c[mt][nt], a[mt], bfr[nt]);
        }
        __syncthreads();
    }

#pragma unroll
    for (int mt = 0; mt < 2; mt++) {
        const int mA = m0 + wm + mt * 16 + g;
#pragma unroll
        for (int i = 0; i < 2; i++) {
            const int m = mA + 8 * i;
            if (m >= MTOT) continue;
            int bq_ = 0, rq = 0;
            if (qkv_mode) { bq_ = m / NPAD; rq = m % NPAD; }
#pragma unroll
            for (int nt = 0; nt < 8; nt++) {
                const int n = n0 + wn + nt * 8 + 2 * tig;
                float2 v = make_float2(c[mt][nt][2 * i + 0] + bias[n],
                                       c[mt][nt][2 * i + 1] + bias[n + 1]);
                if (qkv_mode) {
                    const int hh = n >> 6, d = n & 63;
                    *reinterpret_cast<float2*>(
                        &dst[(((size_t)bq_ * NH + hh) * NPAD + rq) * HD + d]) = v;
                } else {
                    *reinterpret_cast<float2*>(&dst[(size_t)m * 512 + n]) = v;
                }
            }
        }
    }
}

// ---------------------------------------------------------------------------
// Flash attention, fp16 m16n8k16 mma (fp32 accum). CTA: 64 q-rows, 4 warps,
// warp owns 16 q-rows x 64-key tile. Q + P + bias live in registers; K,V in
// half2 smem (K k-major pairs, V transposed key-pairs), stride 36 = no
// conflicts. Bias/mask prefetched at tile top to hide DRAM latency.
// ---------------------------------------------------------------------------
__global__ __launch_bounds__(128) void attn_f16(const float* __restrict__ bias)
{
    __shared__ __align__(16) uint32_t Ks[64 * 36];  // half2 {d even, d odd}
    __shared__ __align__(16) uint32_t Vt[64 * 36];  // half2 {key even, key odd}

    const int tid  = threadIdx.x;
    const int lane = tid & 31, warp = tid >> 5;
    const int g = lane >> 2, tig = lane & 3;
    const int qt = blockIdx.x, h = blockIdx.y, b = blockIdx.z;
    const int qbase = qt * 64, slab = warp * 16;
    const int row0 = qbase + slab + g;
    const int row1 = row0 + 8;
    const bool ok0 = row0 < NPAD, ok1 = row1 < NPAD;

    const float* qptr = g_q + (size_t)((b * NH + h) * NPAD) * HD;
    const float* kptr = g_k + (size_t)((b * NH + h) * NPAD) * HD;
    const float* vptr = g_v + (size_t)((b * NH + h) * NPAD) * HD;
    const float* bptr = bias + (size_t)(b * NH + h) * NPAD * NPAD;

    // Q fragments in registers (half2), once
    uint32_t qf[4][4];
#pragma unroll
    for (int kc = 0; kc < 4; kc++) {
        const int d0 = 16 * kc + 2 * tig;
#pragma unroll
        for (int hf = 0; hf < 2; hf++) {
            const int d = d0 + 8 * hf;
            float2 v0 = ok0 ? *reinterpret_cast<const float2*>(&qptr[(size_t)row0 * HD + d])
                            : make_float2(0.f, 0.f);
            float2 v1 = ok1 ? *reinterpret_cast<const float2*>(&qptr[(size_t)row1 * HD + d])
                            : make_float2(0.f, 0.f);
            qf[kc][2 * hf + 0] = f2h2(v0.x, v0.y);
            qf[kc][2 * hf + 1] = f2h2(v1.x, v1.y);
        }
    }

    float mrow[2] = {-1e30f, -1e30f}, lsum[2] = {0.f, 0.f};
    float o[8][4];
#pragma unroll
    for (int nt = 0; nt < 8; nt++)
#pragma unroll
        for (int e = 0; e < 4; e++) o[nt][e] = 0.f;

    for (int kt = 0; kt < 17; kt++) {
        const int kbase = kt * 64;

        // ---- prefetch bias + mask into registers (independent of smem) ----
        float bv[8][4];
#pragma unroll
        for (int nt = 0; nt < 8; nt++) {
            const int c0 = kbase + 8 * nt + 2 * tig;
            const float* br0 = bptr + (size_t)row0 * NPAD;
            const float* br1 = bptr + (size_t)row1 * NPAD;
            bv[nt][0] = (ok0 && c0     < NPAD) ? __ldg(&br0[c0])     : 0.f;
            bv[nt][1] = (ok0 && c0 + 1 < NPAD) ? __ldg(&br0[c0 + 1]) : 0.f;
            bv[nt][2] = (ok1 && c0     < NPAD) ? __ldg(&br1[c0])     : 0.f;
            bv[nt][3] = (ok1 && c0 + 1 < NPAD) ? __ldg(&br1[c0 + 1]) : 0.f;
        }
        uint32_t mw[2][2];
        mw[0][0] = ok0 ? __ldg(&g_mbits[((size_t)b * NPAD + row0) * MWORDS + 2 * kt])     : 0u;
        mw[0][1] = ok0 ? __ldg(&g_mbits[((size_t)b * NPAD + row0) * MWORDS + 2 * kt + 1]) : 0u;
        mw[1][0] = ok1 ? __ldg(&g_mbits[((size_t)b * NPAD + row1) * MWORDS + 2 * kt])     : 0u;
        mw[1][1] = ok1 ? __ldg(&g_mbits[((size_t)b * NPAD + row1) * MWORDS + 2 * kt + 1]) : 0u;

        // ---- stage K (k-major half2) and V (transposed half2) ----
#pragma unroll
        for (int it = 0; it < 8; it++) {
            const int idx = it * 128 + tid;
            const int key = idx >> 4, g4 = idx & 15;
            const int gk = kbase + key;
            float4 v = (gk < NPAD) ? *reinterpret_cast<const float4*>(&kptr[(size_t)gk * HD + 4 * g4])
                                   : make_float4(0.f, 0.f, 0.f, 0.f);
            *reinterpret_cast<uint2*>(&Ks[key * 36 + 2 * g4]) =
                make_uint2(f2h2(v.x, v.y), f2h2(v.z, v.w));
        }
#pragma unroll
        for (int it = 0; it < 4; it++) {
            const int idx = it * 128 + tid;
            const int kp = idx & 31, g4 = idx >> 5;   // g4: 0..15
            const int k0 = kbase + 2 * kp;
            float4 a = (k0 < NPAD)     ? *reinterpret_cast<const float4*>(&vptr[(size_t)k0 * HD + 4 * g4])
                                       : make_float4(0.f, 0.f, 0.f, 0.f);
            float4 c = (k0 + 1 < NPAD) ? *reinterpret_cast<const float4*>(&vptr[(size_t)(k0 + 1) * HD + 4 * g4])
                                       : make_float4(0.f, 0.f, 0.f, 0.f);
            Vt[(4 * g4 + 0) * 36 + kp] = f2h2(a.x, c.x);
            Vt[(4 * g4 + 1) * 36 + kp] = f2h2(a.y, c.y);
            Vt[(4 * g4 + 2) * 36 + kp] = f2h2(a.z, c.z);
            Vt[(4 * g4 + 3) * 36 + kp] = f2h2(a.w, c.w);
        }
        __syncthreads();

        // ---- S = Q K^T ----
        float s[8][4];
#pragma unroll
        for (int nt = 0; nt < 8; nt++)
#pragma unroll
            for (int e = 0; e < 4; e++) s[nt][e] = 0.f;
#pragma unroll
        for (int kc = 0; kc < 4; kc++) {
#pragma unroll
            for (int nt = 0; nt < 8; nt++) {
                uint32_t bb[2];
                bb[0] = Ks[(8 * nt + g) * 36 + 8 * kc + tig];
                bb[1] = Ks[(8 * nt + g) * 36 + 8 * kc + tig + 4];
                mma16(s[nt], qf[kc], bb);
            }
        }

        // ---- scale + bias + mask (mask bits already encode all bounds) ----
#pragma unroll
        for (int nt = 0; nt < 8; nt++) {
            const int j0 = 8 * nt + 2 * tig;
            const int w = j0 >> 5;
#pragma unroll
            for (int e = 0; e < 4; e++) {
                const int j = j0 + (e & 1);
                float v = s[nt][e] * 0.125f + bv[nt][e];
                if (!((mw[e >> 1][w] >> (j & 31)) & 1u)) v = -1e30f;
                s[nt][e] = v;
            }
        }

        // ---- online softmax (quad reductions) ----
#pragma unroll
        for (int i = 0; i < 2; i++) {
            float mx = -1e30f;
#pragma unroll
            for (int nt = 0; nt < 8; nt++)
                mx = fmaxf(mx, fmaxf(s[nt][2 * i], s[nt][2 * i + 1]));
            mx = fmaxf(mx, __shfl_xor_sync(0xffffffffu, mx, 1));
            mx = fmaxf(mx, __shfl_xor_sync(0xffffffffu, mx, 2));
            const float mn = fmaxf(mrow[i], mx);
            const float corr = __expf(mrow[i] - mn);
            float rs = 0.f;
#pragma unroll
            for (int nt = 0; nt < 8; nt++) {
                float p0 = (s[nt][2 * i]     > -1e29f) ? __expf(s[nt][2 * i]     - mn) : 0.f;
                float p1 = (s[nt][2 * i + 1] > -1e29f) ? __expf(s[nt][2 * i + 1] - mn) : 0.f;
                s[nt][2 * i] = p0; s[nt][2 * i + 1] = p1;
                rs += p0 + p1;
            }
            rs += __shfl_xor_sync(0xffffffffu, rs, 1);
            rs += __shfl_xor_sync(0xffffffffu, rs, 2);
            mrow[i] = mn;
            lsum[i] = lsum[i] * corr + rs;
#pragma unroll
            for (int nt = 0; nt < 8; nt++) {
                o[nt][2 * i]     *= corr;
                o[nt][2 * i + 1] *= corr;
            }
        }

        // ---- O += P V (P direct from registers as half2 A-fragments) ----
#pragma unroll
        for (int kc = 0; kc < 4; kc++) {
            uint32_t af[4];
            af[0] = f2h2(s[2 * kc][0],     s[2 * kc][1]);
            af[1] = f2h2(s[2 * kc][2],     s[2 * kc][3]);
            af[2] = f2h2(s[2 * kc + 1][0], s[2 * kc + 1][1]);
            af[3] = f2h2(s[2 * kc + 1][2], s[2 * kc + 1][3]);
#pragma unroll
            for (int nt = 0; nt < 8; nt++) {
                uint32_t bb[2];
                bb[0] = Vt[(8 * nt + g) * 36 + 8 * kc + tig];
                bb[1] = Vt[(8 * nt + g) * 36 + 8 * kc + tig + 4];
                mma16(o[nt], af, bb);
            }
        }
        __syncthreads();
    }

    // epilogue: normalize + store [B,NP,H*D]
    const float inv0 = (lsum[0] > 0.f) ? 1.f / lsum[0] : 0.f;
    const float inv1 = (lsum[1] > 0.f) ? 1.f / lsum[1] : 0.f;
    float* obase = g_att + (size_t)b * NPAD * E_DIM + h * HD;
#pragma unroll
    for (int nt = 0; nt < 8; nt++) {
        const int d = nt * 8 + 2 * tig;
        if (ok0)
            *reinterpret_cast<float2*>(&obase[(size_t)row0 * E_DIM + d]) =
                make_float2(o[nt][0] * inv0, o[nt][1] * inv0);
        if (ok1)
            *reinterpret_cast<float2*>(&obase[(size_t)row1 * E_DIM + d]) =
                make_float2(o[nt][2] * inv1, o[nt][3] * inv1);
    }
}

// ---------------------------------------------------------------------------
extern "C" void kernel_launch(void* const* d_in, const int* in_sizes, int n_in,
                              void* d_out, int out_size)
{
    const float* x  = (const float*)d_in[0];
    const float* ab = (const float*)d_in[1];
    const int*   pm = (const int*)d_in[2];
    const float* Wq = (const float*)d_in[3];
    const float* bq = (const float*)d_in[4];
    const float* Wk = (const float*)d_in[5];
    const float* bk = (const float*)d_in[6];
    const float* Wv = (const float*)d_in[7];
    const float* bv = (const float*)d_in[8];
    const float* Wo = (const float*)d_in[9];
    const float* bo = (const float*)d_in[10];
    float* out = (float*)d_out;

    pack_mask<<<(BB * NPAD * MWORDS + 255) / 256, 256>>>(pm);

    dim3 gq(4, 65, 3);
    linear_tf32<<<gq, 256>>>(x, Wq, bq, Wk, bk, Wv, bv, nullptr, 1);

    attn_f16<<<dim3(17, NH, BB), 128>>>(ab);

    dim3 go(4, 65, 1);
    linear_tf32<<<go, 256>>>(nullptr, Wo, bo, nullptr, nullptr, nullptr, nullptr, out, 0);
}